// round 6
// baseline (speedup 1.0000x reference)
#include <cuda_runtime.h>
#include <cuda_bf16.h>
#include <cstdint>

#define NN 100000
#define NE 1600000

// ---------------- scratch (__device__ globals; no allocation) --------------
__device__ int    g_w64;
__device__ int    g_deg[NN];
__device__ int    g_cursor[NN];
__device__ int    g_rowptr[NN + 1];
__device__ int    g_bsum[128];
__device__ int    g_boff[128];
__device__ int    g_csr[NE];
__device__ float  g_inv[NN];
// f32 hidden states (for fast gather in aggregation)
__device__ float4 g_hf[3][(size_t)NN * 32];
// bf16 split planes, row-major [node][128] bf16 = 16 uint4 per row
__device__ uint4  g_meanhi4[(size_t)NN * 16];
__device__ uint4  g_meanlo4[(size_t)NN * 16];
__device__ uint4  g_x0hi4[(size_t)NN * 16];
__device__ uint4  g_x0lo4[(size_t)NN * 16];
__device__ uint4  g_hhi4[3][(size_t)NN * 16];
__device__ uint4  g_hlo4[3][(size_t)NN * 16];
// transposed bf16 weights: [l][mat][split][n=128][k=128] ; row = 16 uint4
__device__ uint4  g_wb4[3 * 2 * 2 * 128 * 16];
// fc weights transposed: [split][n=64][k=384] ; row = 48 uint4
__device__ uint4  g_fw4[2 * 64 * 48];

// ---------------- helpers ---------------------------------------------------
__device__ __forceinline__ float bf2f(unsigned u) { return __uint_as_float(u << 16); }
__device__ __forceinline__ void bsplit(float f, unsigned short& h, unsigned short& l) {
    __nv_bfloat16 bh = __float2bfloat16(f);
    float fh = __bfloat162float(bh);
    __nv_bfloat16 bl = __float2bfloat16(f - fh);
    h = __bfloat16_as_ushort(bh);
    l = __bfloat16_as_ushort(bl);
}
__device__ __forceinline__ uint32_t smem_u32(const void* p) {
    return (uint32_t)__cvta_generic_to_shared(p);
}
__device__ __forceinline__ void ldm4(uint32_t* r, uint32_t addr) {
    asm volatile("ldmatrix.sync.aligned.m8n8.x4.shared.b16 {%0,%1,%2,%3}, [%4];"
        : "=r"(r[0]), "=r"(r[1]), "=r"(r[2]), "=r"(r[3]) : "r"(addr));
}
__device__ __forceinline__ void mma16816(float* d, const uint32_t* a, const uint32_t* b) {
    asm volatile("mma.sync.aligned.m16n8k16.row.col.f32.bf16.bf16.f32 "
        "{%0,%1,%2,%3}, {%4,%5,%6,%7}, {%8,%9}, {%0,%1,%2,%3};"
        : "+f"(d[0]), "+f"(d[1]), "+f"(d[2]), "+f"(d[3])
        : "r"(a[0]), "r"(a[1]), "r"(a[2]), "r"(a[3]), "r"(b[0]), "r"(b[1]));
}
__device__ __forceinline__ void cpa16(uint32_t dst, const void* src, int sz) {
    asm volatile("cp.async.cg.shared.global [%0], [%1], 16, %2;"
                 :: "r"(dst), "l"(src), "r"(sz) : "memory");
}
__device__ __forceinline__ void cpa_commit() {
    asm volatile("cp.async.commit_group;" ::: "memory");
}
template <int N>
__device__ __forceinline__ void cpa_wait() {
    asm volatile("cp.async.wait_group %0;" :: "n"(N) : "memory");
}
// B (weights, full K=128): 128 rows x 16 chunks of 16B, XOR swizzle -> conflict-free
__device__ __forceinline__ uint32_t b_off(int n, int ch) {
    return (uint32_t)((n * 16 + (ch ^ (n & 7))) << 4);
}
// A stage (k-chunk 32): 128 rows x 4 chunks of 16B; paired rows share a 128B line
__device__ __forceinline__ uint32_t a_off(int r, int c) {
    return (uint32_t)(((r >> 1) * 8 + ((((r & 1) << 2) + c) ^ ((r >> 1) & 7))) << 4);
}
// legacy 128B-row swizzle (final GEMM)
__device__ __forceinline__ uint32_t sw_off(int row, int chunk) {
    return (uint32_t)(((row << 3) + (chunk ^ (row & 7))) << 4);
}

// ---------------- fused detect + zero --------------------------------------
__global__ void k_init(const long long* __restrict__ ei) {
    int i = blockIdx.x * blockDim.x + threadIdx.x;
    if (i < NN) { g_deg[i] = 0; g_cursor[i] = 0; }
    if (blockIdx.x == 0 && threadIdx.x < 256) {
        __shared__ int bad;
        if (threadIdx.x == 0) bad = 0;
        __syncthreads();
        long long v = ei[threadIdx.x];
        long long u = ei[threadIdx.x + 256];
        if (v < 0 || v >= NN || u < 0 || u >= NN) bad = 1;
        __syncthreads();
        if (threadIdx.x == 0) g_w64 = bad ? 0 : 1;
    }
}
__device__ __forceinline__ int load_idx(const void* ei, size_t i, int w64) {
    if (w64) return (int)((const long long*)ei)[i];
    return ((const int*)ei)[i];
}

// ---------------- CSR build ------------------------------------------------
__global__ void k_count(const void* __restrict__ ei) {
    int e = blockIdx.x * blockDim.x + threadIdx.x;
    if (e < NE) {
        int d = load_idx(ei, (size_t)NE + e, g_w64);
        if ((unsigned)d < (unsigned)NN) atomicAdd(&g_deg[d], 1);
    }
}
__global__ void k_scan1() {
    __shared__ int ws[32];
    int b = blockIdx.x, tid = threadIdx.x, lane = tid & 31, wp = tid >> 5;
    int i = b * 1024 + tid;
    int v = (i < NN) ? g_deg[i] : 0;
    int s = v;
    #pragma unroll
    for (int o = 1; o < 32; o <<= 1) { int t = __shfl_up_sync(0xffffffff, s, o); if (lane >= o) s += t; }
    if (lane == 31) ws[wp] = s;
    __syncthreads();
    if (wp == 0) {
        int t = ws[lane];
        #pragma unroll
        for (int o = 1; o < 32; o <<= 1) { int u = __shfl_up_sync(0xffffffff, t, o); if (lane >= o) t += u; }
        ws[lane] = t;
    }
    __syncthreads();
    int excl = s - v + (wp ? ws[wp - 1] : 0);
    if (i < NN) {
        g_rowptr[i] = excl;
        g_inv[i] = 1.0f / (float)(v > 1 ? v : 1);
    }
    if (tid == 1023) g_bsum[b] = excl + v;
}
__global__ void k_scan2() {
    __shared__ int ws[4];
    int tid = threadIdx.x, lane = tid & 31, wp = tid >> 5;
    const int nb = (NN + 1023) >> 10;
    int v = (tid < nb) ? g_bsum[tid] : 0;
    int s = v;
    #pragma unroll
    for (int o = 1; o < 32; o <<= 1) { int t = __shfl_up_sync(0xffffffff, s, o); if (lane >= o) s += t; }
    if (lane == 31) ws[wp] = s;
    __syncthreads();
    if (tid == 0) { int c = 0; for (int k = 0; k < 4; k++) { int t = ws[k]; ws[k] = c + t; c += t; } }
    __syncthreads();
    int excl = s - v + (wp ? ws[wp - 1] : 0);
    if (tid < nb) g_boff[tid] = excl;
    if (tid == 127) g_rowptr[NN] = ws[3];
}
__global__ void k_scan3() {
    int i = blockIdx.x * blockDim.x + threadIdx.x;
    if (i < NN) g_rowptr[i] += g_boff[i >> 10];
}
__global__ void k_fill(const void* __restrict__ ei) {
    int e = blockIdx.x * blockDim.x + threadIdx.x;
    if (e < NE) {
        int w64 = g_w64;
        int d = load_idx(ei, (size_t)NE + e, w64);
        int s = load_idx(ei, (size_t)e, w64);
        if ((unsigned)d < (unsigned)NN && (unsigned)s < (unsigned)NN) {
            int pos = g_rowptr[d] + atomicAdd(&g_cursor[d], 1);
            if (pos < NE) g_csr[pos] = s;
        }
    }
}

// ---------------- weight / input conversion --------------------------------
__global__ void k_prepw(const float* __restrict__ Wl, const float* __restrict__ Wr,
                        const float* __restrict__ fw) {
    int id = blockIdx.x * blockDim.x + threadIdx.x;
    if (id < 3 * 2 * 128 * 128) {
        int l = id >> 15, r = id & 32767;
        int mat = r >> 14, r2 = r & 16383;
        int n = r2 >> 7, k = r2 & 127;
        const float* W = mat ? Wr : Wl;
        float w = W[(size_t)l * 16384 + k * 128 + n];
        unsigned short hs, ls; bsplit(w, hs, ls);
        unsigned short* wp = (unsigned short*)g_wb4;
        wp[(size_t)(((l * 2 + mat) * 2 + 0) * 128 + n) * 128 + k] = hs;
        wp[(size_t)(((l * 2 + mat) * 2 + 1) * 128 + n) * 128 + k] = ls;
    } else {
        int id2 = id - 3 * 2 * 128 * 128;
        if (id2 < 384 * 64) {
            int k = id2 >> 6, n = id2 & 63;
            float w = fw[(size_t)k * 64 + n];
            unsigned short hs, ls; bsplit(w, hs, ls);
            unsigned short* fp = (unsigned short*)g_fw4;
            fp[(size_t)(0 * 64 + n) * 384 + k] = hs;
            fp[(size_t)(1 * 64 + n) * 384 + k] = ls;
        }
    }
}
__global__ void k_splitx0(const float* __restrict__ x) {
    size_t t = (size_t)blockIdx.x * blockDim.x + threadIdx.x;
    if (t >= (size_t)NN * 32) return;
    float4 v = ((const float4*)x)[t];
    unsigned short h0, l0, h1, l1, h2, l2, h3, l3;
    bsplit(v.x, h0, l0); bsplit(v.y, h1, l1); bsplit(v.z, h2, l2); bsplit(v.w, h3, l3);
    ((uint2*)g_x0hi4)[t] = make_uint2((unsigned)h0 | ((unsigned)h1 << 16), (unsigned)h2 | ((unsigned)h3 << 16));
    ((uint2*)g_x0lo4)[t] = make_uint2((unsigned)l0 | ((unsigned)l1 << 16), (unsigned)l2 | ((unsigned)l3 << 16));
}

// ---------------- mean aggregation: warp per node, MLP-4 f32 gather --------
__global__ void __launch_bounds__(256) k_agg(const float* __restrict__ x0, int layer) {
    int gt = blockIdx.x * blockDim.x + threadIdx.x;
    int wp = gt >> 5, lane = gt & 31;
    if (wp >= NN) return;
    int s = g_rowptr[wp], e = g_rowptr[wp + 1];
    const float4* x4 = (layer == 0) ? (const float4*)x0 : g_hf[layer - 1];
    float a0 = 0.f, a1 = 0.f, a2 = 0.f, a3 = 0.f;
    float b0 = 0.f, b1 = 0.f, b2 = 0.f, b3 = 0.f;
    int p = s;
    for (; p + 3 < e; p += 4) {
        // batch the index loads first (independent), then 4 outstanding gathers
        int j0 = __ldg(&g_csr[p]);
        int j1 = __ldg(&g_csr[p + 1]);
        int j2 = __ldg(&g_csr[p + 2]);
        int j3 = __ldg(&g_csr[p + 3]);
        float4 v0 = __ldg(&x4[(size_t)j0 * 32 + lane]);
        float4 v1 = __ldg(&x4[(size_t)j1 * 32 + lane]);
        float4 v2 = __ldg(&x4[(size_t)j2 * 32 + lane]);
        float4 v3 = __ldg(&x4[(size_t)j3 * 32 + lane]);
        a0 += v0.x; a1 += v0.y; a2 += v0.z; a3 += v0.w;
        b0 += v1.x; b1 += v1.y; b2 += v1.z; b3 += v1.w;
        a0 += v2.x; a1 += v2.y; a2 += v2.z; a3 += v2.w;
        b0 += v3.x; b1 += v3.y; b2 += v3.z; b3 += v3.w;
    }
    if (p + 1 < e) {
        int j0 = __ldg(&g_csr[p]);
        int j1 = __ldg(&g_csr[p + 1]);
        float4 v0 = __ldg(&x4[(size_t)j0 * 32 + lane]);
        float4 v1 = __ldg(&x4[(size_t)j1 * 32 + lane]);
        a0 += v0.x; a1 += v0.y; a2 += v0.z; a3 += v0.w;
        b0 += v1.x; b1 += v1.y; b2 += v1.z; b3 += v1.w;
        p += 2;
    }
    if (p < e) {
        int j = __ldg(&g_csr[p]);
        float4 v = __ldg(&x4[(size_t)j * 32 + lane]);
        a0 += v.x; a1 += v.y; a2 += v.z; a3 += v.w;
    }
    a0 += b0; a1 += b1; a2 += b2; a3 += b3;
    float inv = g_inv[wp];
    a0 *= inv; a1 *= inv; a2 *= inv; a3 *= inv;
    unsigned short h0, l0, h1, l1, h2, l2, h3, l3;
    bsplit(a0, h0, l0); bsplit(a1, h1, l1); bsplit(a2, h2, l2); bsplit(a3, h3, l3);
    ((uint2*)g_meanhi4)[(size_t)wp * 32 + lane] =
        make_uint2((unsigned)h0 | ((unsigned)h1 << 16), (unsigned)h2 | ((unsigned)h3 << 16));
    ((uint2*)g_meanlo4)[(size_t)wp * 32 + lane] =
        make_uint2((unsigned)l0 | ((unsigned)l1 << 16), (unsigned)l2 | ((unsigned)l3 << 16));
}

// ---------------- layer GEMM (mma.sync bf16, cp.async pipelined) -----------
// CTA tile M=128,N=128; 8 warps 4x2 (warp 32x64).
// smem: B full-K resident: 4 planes x 32KB = 128KB at offset 0
//       A double-buffered k32 stages: 2 x (4 planes x 8KB) = 64KB at 131072
#define SMEM_L (131072 + 65536)
__global__ void __launch_bounds__(256, 1) k_gemm_layer(const float* __restrict__ bias, int layer) {
    extern __shared__ char smem[];
    uint32_t sb = smem_u32(smem);
    const int tid = threadIdx.x;
    const int wid = tid >> 5, lane = tid & 31;
    const int m0 = blockIdx.x * 128;
    const int warp_m = wid & 3, warp_n = wid >> 2;

    const uint4* srcA[4] = {
        g_meanhi4, g_meanlo4,
        (layer == 0) ? g_x0hi4 : g_hhi4[layer - 1],
        (layer == 0) ? g_x0lo4 : g_hlo4[layer - 1]
    };

    // ---- B load (once, full K): 4 planes x 2048 chunks
    {
        const uint4* wbase = g_wb4 + (size_t)(layer * 2) * 2 * 128 * 16;
        #pragma unroll 8
        for (int u = tid; u < 8192; u += 256) {
            int bpl = u >> 11, rest = u & 2047;
            int n = rest >> 4, c = rest & 15;
            const uint4* src = wbase + (size_t)bpl * 128 * 16 + n * 16 + c;
            cpa16(sb + bpl * 32768 + b_off(n, c), src, 16);
        }
    }
    // ---- A stage loader (k-chunk kc -> stage s)
    auto loadA = [&](int kc, int s) {
        uint32_t stb = sb + 131072 + s * 32768;
        #pragma unroll 8
        for (int u = tid; u < 2048; u += 256) {
            int apl = u >> 9, rest = u & 511;
            int r = rest >> 2, c = rest & 3;
            int rg = m0 + r;
            int ok = rg < NN;
            const uint4* src = srcA[apl] + (size_t)(ok ? rg : 0) * 16 + kc * 4 + c;
            cpa16(stb + apl * 8192 + a_off(r, c), src, ok ? 16 : 0);
        }
    };
    loadA(0, 0);
    cpa_commit();

    float acc[2][8][4];
    #pragma unroll
    for (int mt = 0; mt < 2; ++mt)
        #pragma unroll
        for (int nt = 0; nt < 8; ++nt)
            { acc[mt][nt][0]=0.f; acc[mt][nt][1]=0.f; acc[mt][nt][2]=0.f; acc[mt][nt][3]=0.f; }

    const int chA[6] = {0, 1, 0, 2, 3, 2};
    const int chB[6] = {0, 0, 1, 2, 2, 3};

    for (int kc = 0; kc < 4; ++kc) {
        if (kc < 3) { loadA(kc + 1, (kc + 1) & 1); cpa_commit(); }
        if (kc < 3) cpa_wait<1>(); else cpa_wait<0>();
        __syncthreads();

        uint32_t stb = sb + 131072 + (kc & 1) * 32768;
        #pragma unroll
        for (int ch = 0; ch < 6; ++ch) {
            uint32_t baseA = stb + chA[ch] * 8192;
            uint32_t baseB = sb + chB[ch] * 32768;
            #pragma unroll
            for (int ks = 0; ks < 2; ++ks) {
                int cs  = ks * 2 + (lane >> 4);           // A chunk in stage (0..3)
                int bch = kc * 4 + ks * 2 + (lane >> 4);  // B chunk full-K (0..15)
                uint32_t a[2][4];
                #pragma unroll
                for (int mt = 0; mt < 2; ++mt) {
                    int row = warp_m * 32 + mt * 16 + (lane & 15);
                    ldm4(a[mt], baseA + a_off(row, cs));
                }
                uint32_t b[8][2];
                #pragma unroll
                for (int np = 0; np < 4; ++np) {
                    int row = warp_n * 64 + np * 16 + (lane & 7) + (((lane >> 3) & 1) << 3);
                    uint32_t t[4];
                    ldm4(t, baseB + b_off(row, bch));
                    b[np * 2][0] = t[0];  b[np * 2][1] = t[2];
                    b[np * 2 + 1][0] = t[1];  b[np * 2 + 1][1] = t[3];
                }
                #pragma unroll
                for (int mt = 0; mt < 2; ++mt)
                    #pragma unroll
                    for (int nt = 0; nt < 8; ++nt)
                        mma16816(acc[mt][nt], a[mt], b[nt]);
            }
        }
        __syncthreads();
    }

    // epilogue: bias + relu; store f32 h (for gather) + bf16 splits (for GEMM)
    uint32_t* oh = (uint32_t*)g_hhi4[layer];
    uint32_t* ol = (uint32_t*)g_hlo4[layer];
    float*    of = (float*)g_hf[layer];
    #pragma unroll
    for (int mt = 0; mt < 2; ++mt) {
        int row0 = m0 + warp_m * 32 + mt * 16 + (lane >> 2);
        #pragma unroll
        for (int nt = 0; nt < 8; ++nt) {
            int col = warp_n * 64 + nt * 8 + (lane & 3) * 2;
            float b0 = __ldg(&bias[col]), b1 = __ldg(&bias[col + 1]);
            #pragma unroll
            for (int h = 0; h < 2; ++h) {
                int row = row0 + h * 8;
                if (row < NN) {
                    float f0 = fmaxf(acc[mt][nt][h * 2 + 0] + b0, 0.f);
                    float f1 = fmaxf(acc[mt][nt][h * 2 + 1] + b1, 0.f);
                    unsigned short h0, l0, h1, l1;
                    bsplit(f0, h0, l0); bsplit(f1, h1, l1);
                    size_t idx = (size_t)row * 64 + (col >> 1);
                    oh[idx] = (unsigned)h0 | ((unsigned)h1 << 16);
                    ol[idx] = (unsigned)l0 | ((unsigned)l1 << 16);
                    *(float2*)&of[(size_t)row * 128 + col] = make_float2(f0, f1);
                }
            }
        }
    }
}

// ---------------- final JK GEMM (mma.sync): [N,384]@[384,64] + fc_b --------
#define SMEM_F (2 * 16384 + 2 * 8192)
__global__ void __launch_bounds__(256, 1) k_gemm_final(const float* __restrict__ fb,
                                                       float* __restrict__ out) {
    extern __shared__ char smem[];
    uint32_t sb = smem_u32(smem);
    const int tid = threadIdx.x;
    const int wid = tid >> 5, lane = tid & 31;
    const int m0 = blockIdx.x * 128;

    float acc[8][4];
    #pragma unroll
    for (int nt = 0; nt < 8; ++nt)
        { acc[nt][0]=0.f; acc[nt][1]=0.f; acc[nt][2]=0.f; acc[nt][3]=0.f; }

    for (int cc = 0; cc < 6; ++cc) {
        int l = cc >> 1, kc = cc & 1;
        #pragma unroll 4
        for (int u = tid; u < 2 * 1024; u += 256) {
            int plane = u >> 10, r = (u >> 3) & 127, c = u & 7;
            const uint4* src = plane ? g_hlo4[l] : g_hhi4[l];
            int rg = m0 + r;
            int ok = rg < NN;
            cpa16(sb + plane * 16384 + sw_off(r, c),
                  src + (size_t)(ok ? rg : 0) * 16 + kc * 8 + c, ok ? 16 : 0);
        }
        #pragma unroll 2
        for (int u = tid; u < 2 * 512; u += 256) {
            int sp = u >> 9, r = (u >> 3) & 63, c = u & 7;
            const uint4* src = g_fw4 + (size_t)sp * 64 * 48;
            cpa16(sb + 32768 + sp * 8192 + sw_off(r, c),
                  src + (size_t)r * 48 + cc * 8 + c, 16);
        }
        cpa_commit();
        cpa_wait<0>();
        __syncthreads();

        const int fA[3] = {0, 0, 1}, fB[3] = {0, 1, 0};
        #pragma unroll
        for (int ch = 0; ch < 3; ++ch) {
            uint32_t baseA = sb + fA[ch] * 16384;
            uint32_t baseB = sb + 32768 + fB[ch] * 8192;
            #pragma unroll
            for (int ks = 0; ks < 4; ++ks) {
                int ch16 = ks * 2 + (lane >> 4);
                uint32_t a[4];
                {
                    int row = wid * 16 + (lane & 15);
                    ldm4(a, baseA + sw_off(row, ch16));
                }
                uint32_t b[8][2];
                #pragma unroll
                for (int np = 0; np < 4; ++np) {
                    int row = np * 16 + (lane & 7) + (((lane >> 3) & 1) << 3);
                    uint32_t t[4];
                    ldm4(t, baseB + sw_off(row, ch16));
                    b[np * 2][0] = t[0];  b[np * 2][1] = t[2];
                    b[np * 2 + 1][0] = t[1];  b[np * 2 + 1][1] = t[3];
                }
                #pragma unroll
                for (int nt = 0; nt < 8; ++nt)
                    mma16816(acc[nt], a, b[nt]);
            }
        }
        __syncthreads();
    }

    int row0 = m0 + wid * 16 + (lane >> 2);
    #pragma unroll
    for (int nt = 0; nt < 8; ++nt) {
        int col = nt * 8 + (lane & 3) * 2;
        float b0 = __ldg(&fb[col]), b1 = __ldg(&fb[col + 1]);
        #pragma unroll
        for (int h = 0; h < 2; ++h) {
            int row = row0 + h * 8;
            if (row < NN) {
                float2 o;
                o.x = acc[nt][h * 2 + 0] + b0;
                o.y = acc[nt][h * 2 + 1] + b1;
                *(float2*)&out[(size_t)row * 64 + col] = o;
            }
        }
    }
}

// ---------------- launch ----------------------------------------------------
extern "C" void kernel_launch(void* const* d_in, const int* in_sizes, int n_in,
                              void* d_out, int out_size) {
    const float* x  = (const float*)d_in[0];
    const void*  ei = d_in[1];
    const float* Wl = (const float*)d_in[2];
    const float* Wr = (const float*)d_in[3];
    const float* b  = (const float*)d_in[4];
    const float* fw = (const float*)d_in[5];
    const float* fb = (const float*)d_in[6];
    float* out = (float*)d_out;

    cudaFuncSetAttribute(k_gemm_layer, cudaFuncAttributeMaxDynamicSharedMemorySize, SMEM_L);
    cudaFuncSetAttribute(k_gemm_final, cudaFuncAttributeMaxDynamicSharedMemorySize, SMEM_F);

    k_init  <<<(NN + 1023) / 1024, 1024>>>((const long long*)ei);
    k_count <<<(NE + 255) / 256, 256>>>(ei);
    k_scan1 <<<(NN + 1023) / 1024, 1024>>>();
    k_scan2 <<<1, 128>>>();
    k_scan3 <<<(NN + 1023) / 1024, 1024>>>();
    k_fill  <<<(NE + 255) / 256, 256>>>(ei);
    k_prepw <<<(3*2*128*128 + 384*64 + 255) / 256, 256>>>(Wl, Wr, fw);
    k_splitx0<<<(NN * 32 + 255) / 256, 256>>>(x);

    const int gemm_blocks = (NN + 127) / 128;
    for (int l = 0; l < 3; ++l) {
        k_agg<<<(NN * 32 + 255) / 256, 256>>>(x, l);
        k_gemm_layer<<<gemm_blocks, 256, SMEM_L>>>(b + (size_t)l * 128, l);
    }
    k_gemm_final<<<gemm_blocks, 256, SMEM_F>>>(fb, out);
}

// round 7
// speedup vs baseline: 1.0594x; 1.0594x over previous
#include <cuda_runtime.h>
#include <cuda_bf16.h>
#include <cuda_fp16.h>
#include <cstdint>

#define NN 100000
#define NE 1600000

// ---------------- scratch (__device__ globals; no allocation) --------------
__device__ int    g_w64;
__device__ int    g_deg[NN];
__device__ int    g_cursor[NN];
__device__ int    g_rowptr[NN + 1];
__device__ int    g_bsum[128];
__device__ int    g_boff[128];
__device__ int    g_csr[NE];
__device__ float  g_inv[NN];
// fp16 gather planes: [node][128] half = 32 uint2 per row
__device__ uint2  g_xh[(size_t)NN * 32];
__device__ uint2  g_hh[3][(size_t)NN * 32];
// bf16 split planes, row-major [node][128] bf16 = 16 uint4 per row
__device__ uint4  g_meanhi4[(size_t)NN * 16];
__device__ uint4  g_meanlo4[(size_t)NN * 16];
__device__ uint4  g_x0hi4[(size_t)NN * 16];
__device__ uint4  g_x0lo4[(size_t)NN * 16];
__device__ uint4  g_hhi4[3][(size_t)NN * 16];
__device__ uint4  g_hlo4[3][(size_t)NN * 16];
// transposed bf16 weights: [l][mat][split][n=128][k=128] ; row = 16 uint4
__device__ uint4  g_wb4[3 * 2 * 2 * 128 * 16];
// fc weights transposed: [split][n=64][k=384] ; row = 48 uint4
__device__ uint4  g_fw4[2 * 64 * 48];

// ---------------- helpers ---------------------------------------------------
__device__ __forceinline__ void bsplit(float f, unsigned short& h, unsigned short& l) {
    __nv_bfloat16 bh = __float2bfloat16(f);
    float fh = __bfloat162float(bh);
    __nv_bfloat16 bl = __float2bfloat16(f - fh);
    h = __bfloat16_as_ushort(bh);
    l = __bfloat16_as_ushort(bl);
}
__device__ __forceinline__ uint32_t pack_h2(float a, float b) {
    __half2 p = __floats2half2_rn(a, b);
    return *reinterpret_cast<uint32_t*>(&p);
}
__device__ __forceinline__ float2 unpack_h2(uint32_t u) {
    return __half22float2(*reinterpret_cast<const __half2*>(&u));
}
__device__ __forceinline__ uint32_t smem_u32(const void* p) {
    return (uint32_t)__cvta_generic_to_shared(p);
}
__device__ __forceinline__ void ldm4(uint32_t* r, uint32_t addr) {
    asm volatile("ldmatrix.sync.aligned.m8n8.x4.shared.b16 {%0,%1,%2,%3}, [%4];"
        : "=r"(r[0]), "=r"(r[1]), "=r"(r[2]), "=r"(r[3]) : "r"(addr));
}
__device__ __forceinline__ void mma16816(float* d, const uint32_t* a, const uint32_t* b) {
    asm volatile("mma.sync.aligned.m16n8k16.row.col.f32.bf16.bf16.f32 "
        "{%0,%1,%2,%3}, {%4,%5,%6,%7}, {%8,%9}, {%0,%1,%2,%3};"
        : "+f"(d[0]), "+f"(d[1]), "+f"(d[2]), "+f"(d[3])
        : "r"(a[0]), "r"(a[1]), "r"(a[2]), "r"(a[3]), "r"(b[0]), "r"(b[1]));
}
__device__ __forceinline__ void cpa16(uint32_t dst, const void* src, int sz) {
    asm volatile("cp.async.cg.shared.global [%0], [%1], 16, %2;"
                 :: "r"(dst), "l"(src), "r"(sz) : "memory");
}
__device__ __forceinline__ void cpa_commit() {
    asm volatile("cp.async.commit_group;" ::: "memory");
}
template <int N>
__device__ __forceinline__ void cpa_wait() {
    asm volatile("cp.async.wait_group %0;" :: "n"(N) : "memory");
}
__device__ __forceinline__ uint32_t b_off(int n, int ch) {
    return (uint32_t)((n * 16 + (ch ^ (n & 7))) << 4);
}
__device__ __forceinline__ uint32_t a_off(int r, int c) {
    return (uint32_t)(((r >> 1) * 8 + ((((r & 1) << 2) + c) ^ ((r >> 1) & 7))) << 4);
}
__device__ __forceinline__ uint32_t sw_off(int row, int chunk) {
    return (uint32_t)(((row << 3) + (chunk ^ (row & 7))) << 4);
}

// ---------------- fused detect + zero --------------------------------------
__global__ void k_init(const long long* __restrict__ ei) {
    int i = blockIdx.x * blockDim.x + threadIdx.x;
    if (i < NN) { g_deg[i] = 0; g_cursor[i] = 0; }
    if (blockIdx.x == 0 && threadIdx.x < 256) {
        __shared__ int bad;
        if (threadIdx.x == 0) bad = 0;
        __syncthreads();
        long long v = ei[threadIdx.x];
        long long u = ei[threadIdx.x + 256];
        if (v < 0 || v >= NN || u < 0 || u >= NN) bad = 1;
        __syncthreads();
        if (threadIdx.x == 0) g_w64 = bad ? 0 : 1;
    }
}
__device__ __forceinline__ int load_idx(const void* ei, size_t i, int w64) {
    if (w64) return (int)((const long long*)ei)[i];
    return ((const int*)ei)[i];
}

// ---------------- CSR build ------------------------------------------------
__global__ void k_count(const void* __restrict__ ei) {
    int e = blockIdx.x * blockDim.x + threadIdx.x;
    if (e < NE) {
        int d = load_idx(ei, (size_t)NE + e, g_w64);
        if ((unsigned)d < (unsigned)NN) atomicAdd(&g_deg[d], 1);
    }
}
__global__ void k_scan1() {
    __shared__ int ws[32];
    int b = blockIdx.x, tid = threadIdx.x, lane = tid & 31, wp = tid >> 5;
    int i = b * 1024 + tid;
    int v = (i < NN) ? g_deg[i] : 0;
    int s = v;
    #pragma unroll
    for (int o = 1; o < 32; o <<= 1) { int t = __shfl_up_sync(0xffffffff, s, o); if (lane >= o) s += t; }
    if (lane == 31) ws[wp] = s;
    __syncthreads();
    if (wp == 0) {
        int t = ws[lane];
        #pragma unroll
        for (int o = 1; o < 32; o <<= 1) { int u = __shfl_up_sync(0xffffffff, t, o); if (lane >= o) t += u; }
        ws[lane] = t;
    }
    __syncthreads();
    int excl = s - v + (wp ? ws[wp - 1] : 0);
    if (i < NN) {
        g_rowptr[i] = excl;
        g_inv[i] = 1.0f / (float)(v > 1 ? v : 1);
    }
    if (tid == 1023) g_bsum[b] = excl + v;
}
__global__ void k_scan2() {
    __shared__ int ws[4];
    int tid = threadIdx.x, lane = tid & 31, wp = tid >> 5;
    const int nb = (NN + 1023) >> 10;
    int v = (tid < nb) ? g_bsum[tid] : 0;
    int s = v;
    #pragma unroll
    for (int o = 1; o < 32; o <<= 1) { int t = __shfl_up_sync(0xffffffff, s, o); if (lane >= o) s += t; }
    if (lane == 31) ws[wp] = s;
    __syncthreads();
    if (tid == 0) { int c = 0; for (int k = 0; k < 4; k++) { int t = ws[k]; ws[k] = c + t; c += t; } }
    __syncthreads();
    int excl = s - v + (wp ? ws[wp - 1] : 0);
    if (tid < nb) g_boff[tid] = excl;
    if (tid == 127) g_rowptr[NN] = ws[3];
}
__global__ void k_scan3() {
    int i = blockIdx.x * blockDim.x + threadIdx.x;
    if (i < NN) g_rowptr[i] += g_boff[i >> 10];
}
__global__ void k_fill(const void* __restrict__ ei) {
    int e = blockIdx.x * blockDim.x + threadIdx.x;
    if (e < NE) {
        int w64 = g_w64;
        int d = load_idx(ei, (size_t)NE + e, w64);
        int s = load_idx(ei, (size_t)e, w64);
        if ((unsigned)d < (unsigned)NN && (unsigned)s < (unsigned)NN) {
            int pos = g_rowptr[d] + atomicAdd(&g_cursor[d], 1);
            if (pos < NE) g_csr[pos] = s;
        }
    }
}

// ---------------- weight / input conversion --------------------------------
__global__ void k_prepw(const float* __restrict__ Wl, const float* __restrict__ Wr,
                        const float* __restrict__ fw) {
    int id = blockIdx.x * blockDim.x + threadIdx.x;
    if (id < 3 * 2 * 128 * 128) {
        int l = id >> 15, r = id & 32767;
        int mat = r >> 14, r2 = r & 16383;
        int n = r2 >> 7, k = r2 & 127;
        const float* W = mat ? Wr : Wl;
        float w = W[(size_t)l * 16384 + k * 128 + n];
        unsigned short hs, ls; bsplit(w, hs, ls);
        unsigned short* wp = (unsigned short*)g_wb4;
        wp[(size_t)(((l * 2 + mat) * 2 + 0) * 128 + n) * 128 + k] = hs;
        wp[(size_t)(((l * 2 + mat) * 2 + 1) * 128 + n) * 128 + k] = ls;
    } else {
        int id2 = id - 3 * 2 * 128 * 128;
        if (id2 < 384 * 64) {
            int k = id2 >> 6, n = id2 & 63;
            float w = fw[(size_t)k * 64 + n];
            unsigned short hs, ls; bsplit(w, hs, ls);
            unsigned short* fp = (unsigned short*)g_fw4;
            fp[(size_t)(0 * 64 + n) * 384 + k] = hs;
            fp[(size_t)(1 * 64 + n) * 384 + k] = ls;
        }
    }
}
__global__ void k_splitx0(const float* __restrict__ x) {
    size_t t = (size_t)blockIdx.x * blockDim.x + threadIdx.x;
    if (t >= (size_t)NN * 32) return;
    float4 v = ((const float4*)x)[t];
    unsigned short h0, l0, h1, l1, h2, l2, h3, l3;
    bsplit(v.x, h0, l0); bsplit(v.y, h1, l1); bsplit(v.z, h2, l2); bsplit(v.w, h3, l3);
    ((uint2*)g_x0hi4)[t] = make_uint2((unsigned)h0 | ((unsigned)h1 << 16), (unsigned)h2 | ((unsigned)h3 << 16));
    ((uint2*)g_x0lo4)[t] = make_uint2((unsigned)l0 | ((unsigned)l1 << 16), (unsigned)l2 | ((unsigned)l3 << 16));
    g_xh[t] = make_uint2(pack_h2(v.x, v.y), pack_h2(v.z, v.w));
}

// ---------------- mean aggregation: warp per node, fp16 gather, MLP-2 ------
__global__ void __launch_bounds__(256) k_agg(int layer) {
    int gt = blockIdx.x * blockDim.x + threadIdx.x;
    int wp = gt >> 5, lane = gt & 31;
    if (wp >= NN) return;
    int s = g_rowptr[wp], e = g_rowptr[wp + 1];
    const uint2* xh = (layer == 0) ? g_xh : g_hh[layer - 1];
    float a0 = 0.f, a1 = 0.f, a2 = 0.f, a3 = 0.f;
    float b0 = 0.f, b1 = 0.f, b2 = 0.f, b3 = 0.f;
    int p = s;
    for (; p + 1 < e; p += 2) {
        int j0 = __ldg(&g_csr[p]);
        int j1 = __ldg(&g_csr[p + 1]);
        uint2 u0 = __ldg(&xh[(size_t)j0 * 32 + lane]);
        uint2 u1 = __ldg(&xh[(size_t)j1 * 32 + lane]);
        float2 f0 = unpack_h2(u0.x), f1 = unpack_h2(u0.y);
        float2 g0 = unpack_h2(u1.x), g1 = unpack_h2(u1.y);
        a0 += f0.x; a1 += f0.y; a2 += f1.x; a3 += f1.y;
        b0 += g0.x; b1 += g0.y; b2 += g1.x; b3 += g1.y;
    }
    if (p < e) {
        int j = __ldg(&g_csr[p]);
        uint2 u = __ldg(&xh[(size_t)j * 32 + lane]);
        float2 f0 = unpack_h2(u.x), f1 = unpack_h2(u.y);
        a0 += f0.x; a1 += f0.y; a2 += f1.x; a3 += f1.y;
    }
    a0 += b0; a1 += b1; a2 += b2; a3 += b3;
    float inv = g_inv[wp];
    a0 *= inv; a1 *= inv; a2 *= inv; a3 *= inv;
    unsigned short h0, l0, h1, l1, h2, l2, h3, l3;
    bsplit(a0, h0, l0); bsplit(a1, h1, l1); bsplit(a2, h2, l2); bsplit(a3, h3, l3);
    ((uint2*)g_meanhi4)[(size_t)wp * 32 + lane] =
        make_uint2((unsigned)h0 | ((unsigned)h1 << 16), (unsigned)h2 | ((unsigned)h3 << 16));
    ((uint2*)g_meanlo4)[(size_t)wp * 32 + lane] =
        make_uint2((unsigned)l0 | ((unsigned)l1 << 16), (unsigned)l2 | ((unsigned)l3 << 16));
}

// ---------------- layer GEMM (mma.sync bf16, cp.async pipelined) -----------
// CTA tile M=128,N=128; 8 warps 4x2 (warp 32x64).
// smem: B full-K resident: 4 planes x 32KB = 128KB at offset 0
//       A double-buffered k32 stages: 2 x (4 planes x 8KB) = 64KB at 131072
#define SMEM_L (131072 + 65536)
__global__ void __launch_bounds__(256, 1) k_gemm_layer(const float* __restrict__ bias, int layer) {
    extern __shared__ char smem[];
    uint32_t sb = smem_u32(smem);
    const int tid = threadIdx.x;
    const int wid = tid >> 5, lane = tid & 31;
    const int m0 = blockIdx.x * 128;
    const int warp_m = wid & 3, warp_n = wid >> 2;

    const uint4* srcA[4] = {
        g_meanhi4, g_meanlo4,
        (layer == 0) ? g_x0hi4 : g_hhi4[layer - 1],
        (layer == 0) ? g_x0lo4 : g_hlo4[layer - 1]
    };

    // ---- B load (once, full K): 4 planes x 2048 chunks
    {
        const uint4* wbase = g_wb4 + (size_t)(layer * 2) * 2 * 128 * 16;
        #pragma unroll 8
        for (int u = tid; u < 8192; u += 256) {
            int bpl = u >> 11, rest = u & 2047;
            int n = rest >> 4, c = rest & 15;
            const uint4* src = wbase + (size_t)bpl * 128 * 16 + n * 16 + c;
            cpa16(sb + bpl * 32768 + b_off(n, c), src, 16);
        }
    }
    // ---- A stage loader (k-chunk kc -> stage s)
    auto loadA = [&](int kc, int s) {
        uint32_t stb = sb + 131072 + s * 32768;
        #pragma unroll 8
        for (int u = tid; u < 2048; u += 256) {
            int apl = u >> 9, rest = u & 511;
            int r = rest >> 2, c = rest & 3;
            int rg = m0 + r;
            int ok = rg < NN;
            const uint4* src = srcA[apl] + (size_t)(ok ? rg : 0) * 16 + kc * 4 + c;
            cpa16(stb + apl * 8192 + a_off(r, c), src, ok ? 16 : 0);
        }
    };
    loadA(0, 0);
    cpa_commit();

    float acc[2][8][4];
    #pragma unroll
    for (int mt = 0; mt < 2; ++mt)
        #pragma unroll
        for (int nt = 0; nt < 8; ++nt)
            { acc[mt][nt][0]=0.f; acc[mt][nt][1]=0.f; acc[mt][nt][2]=0.f; acc[mt][nt][3]=0.f; }

    const int chA[6] = {0, 1, 0, 2, 3, 2};
    const int chB[6] = {0, 0, 1, 2, 2, 3};

    for (int kc = 0; kc < 4; ++kc) {
        if (kc < 3) { loadA(kc + 1, (kc + 1) & 1); cpa_commit(); }
        if (kc < 3) cpa_wait<1>(); else cpa_wait<0>();
        __syncthreads();

        uint32_t stb = sb + 131072 + (kc & 1) * 32768;
        #pragma unroll
        for (int ch = 0; ch < 6; ++ch) {
            uint32_t baseA = stb + chA[ch] * 8192;
            uint32_t baseB = sb + chB[ch] * 32768;
            #pragma unroll
            for (int ks = 0; ks < 2; ++ks) {
                int cs  = ks * 2 + (lane >> 4);           // A chunk in stage (0..3)
                int bch = kc * 4 + ks * 2 + (lane >> 4);  // B chunk full-K (0..15)
                uint32_t a[2][4];
                #pragma unroll
                for (int mt = 0; mt < 2; ++mt) {
                    int row = warp_m * 32 + mt * 16 + (lane & 15);
                    ldm4(a[mt], baseA + a_off(row, cs));
                }
                uint32_t b[8][2];
                #pragma unroll
                for (int np = 0; np < 4; ++np) {
                    int row = warp_n * 64 + np * 16 + (lane & 7) + (((lane >> 3) & 1) << 3);
                    uint32_t t[4];
                    ldm4(t, baseB + b_off(row, bch));
                    b[np * 2][0] = t[0];  b[np * 2][1] = t[2];
                    b[np * 2 + 1][0] = t[1];  b[np * 2 + 1][1] = t[3];
                }
                #pragma unroll
                for (int mt = 0; mt < 2; ++mt)
                    #pragma unroll
                    for (int nt = 0; nt < 8; ++nt)
                        mma16816(acc[mt][nt], a[mt], b[nt]);
            }
        }
        __syncthreads();
    }

    // epilogue: bias + relu; store fp16 (for gather) + bf16 splits (for GEMM)
    uint32_t* oh = (uint32_t*)g_hhi4[layer];
    uint32_t* ol = (uint32_t*)g_hlo4[layer];
    uint32_t* op = (uint32_t*)g_hh[layer];
    #pragma unroll
    for (int mt = 0; mt < 2; ++mt) {
        int row0 = m0 + warp_m * 32 + mt * 16 + (lane >> 2);
        #pragma unroll
        for (int nt = 0; nt < 8; ++nt) {
            int col = warp_n * 64 + nt * 8 + (lane & 3) * 2;
            float b0 = __ldg(&bias[col]), b1 = __ldg(&bias[col + 1]);
            #pragma unroll
            for (int h = 0; h < 2; ++h) {
                int row = row0 + h * 8;
                if (row < NN) {
                    float f0 = fmaxf(acc[mt][nt][h * 2 + 0] + b0, 0.f);
                    float f1 = fmaxf(acc[mt][nt][h * 2 + 1] + b1, 0.f);
                    unsigned short h0, l0, h1, l1;
                    bsplit(f0, h0, l0); bsplit(f1, h1, l1);
                    size_t idx = (size_t)row * 64 + (col >> 1);
                    oh[idx] = (unsigned)h0 | ((unsigned)h1 << 16);
                    ol[idx] = (unsigned)l0 | ((unsigned)l1 << 16);
                    op[idx] = pack_h2(f0, f1);
                }
            }
        }
    }
}

// ---------------- final JK GEMM (mma.sync): [N,384]@[384,64] + fc_b --------
#define SMEM_F (2 * 16384 + 2 * 8192)
__global__ void __launch_bounds__(256, 1) k_gemm_final(const float* __restrict__ fb,
                                                       float* __restrict__ out) {
    extern __shared__ char smem[];
    uint32_t sb = smem_u32(smem);
    const int tid = threadIdx.x;
    const int wid = tid >> 5, lane = tid & 31;
    const int m0 = blockIdx.x * 128;

    float acc[8][4];
    #pragma unroll
    for (int nt = 0; nt < 8; ++nt)
        { acc[nt][0]=0.f; acc[nt][1]=0.f; acc[nt][2]=0.f; acc[nt][3]=0.f; }

    for (int cc = 0; cc < 6; ++cc) {
        int l = cc >> 1, kc = cc & 1;
        #pragma unroll 4
        for (int u = tid; u < 2 * 1024; u += 256) {
            int plane = u >> 10, r = (u >> 3) & 127, c = u & 7;
            const uint4* src = plane ? g_hlo4[l] : g_hhi4[l];
            int rg = m0 + r;
            int ok = rg < NN;
            cpa16(sb + plane * 16384 + sw_off(r, c),
                  src + (size_t)(ok ? rg : 0) * 16 + kc * 8 + c, ok ? 16 : 0);
        }
        #pragma unroll 2
        for (int u = tid; u < 2 * 512; u += 256) {
            int sp = u >> 9, r = (u >> 3) & 63, c = u & 7;
            const uint4* src = g_fw4 + (size_t)sp * 64 * 48;
            cpa16(sb + 32768 + sp * 8192 + sw_off(r, c),
                  src + (size_t)r * 48 + cc * 8 + c, 16);
        }
        cpa_commit();
        cpa_wait<0>();
        __syncthreads();

        const int fA[3] = {0, 0, 1}, fB[3] = {0, 1, 0};
        #pragma unroll
        for (int ch = 0; ch < 3; ++ch) {
            uint32_t baseA = sb + fA[ch] * 16384;
            uint32_t baseB = sb + 32768 + fB[ch] * 8192;
            #pragma unroll
            for (int ks = 0; ks < 4; ++ks) {
                int ch16 = ks * 2 + (lane >> 4);
                uint32_t a[4];
                {
                    int row = wid * 16 + (lane & 15);
                    ldm4(a, baseA + sw_off(row, ch16));
                }
                uint32_t b[8][2];
                #pragma unroll
                for (int np = 0; np < 4; ++np) {
                    int row = np * 16 + (lane & 7) + (((lane >> 3) & 1) << 3);
                    uint32_t t[4];
                    ldm4(t, baseB + sw_off(row, ch16));
                    b[np * 2][0] = t[0];  b[np * 2][1] = t[2];
                    b[np * 2 + 1][0] = t[1];  b[np * 2 + 1][1] = t[3];
                }
                #pragma unroll
                for (int nt = 0; nt < 8; ++nt)
                    mma16816(acc[nt], a, b[nt]);
            }
        }
        __syncthreads();
    }

    int row0 = m0 + wid * 16 + (lane >> 2);
    #pragma unroll
    for (int nt = 0; nt < 8; ++nt) {
        int col = nt * 8 + (lane & 3) * 2;
        float b0 = __ldg(&fb[col]), b1 = __ldg(&fb[col + 1]);
        #pragma unroll
        for (int h = 0; h < 2; ++h) {
            int row = row0 + h * 8;
            if (row < NN) {
                float2 o;
                o.x = acc[nt][h * 2 + 0] + b0;
                o.y = acc[nt][h * 2 + 1] + b1;
                *(float2*)&out[(size_t)row * 64 + col] = o;
            }
        }
    }
}

// ---------------- launch ----------------------------------------------------
extern "C" void kernel_launch(void* const* d_in, const int* in_sizes, int n_in,
                              void* d_out, int out_size) {
    const float* x  = (const float*)d_in[0];
    const void*  ei = d_in[1];
    const float* Wl = (const float*)d_in[2];
    const float* Wr = (const float*)d_in[3];
    const float* b  = (const float*)d_in[4];
    const float* fw = (const float*)d_in[5];
    const float* fb = (const float*)d_in[6];
    float* out = (float*)d_out;

    cudaFuncSetAttribute(k_gemm_layer, cudaFuncAttributeMaxDynamicSharedMemorySize, SMEM_L);
    cudaFuncSetAttribute(k_gemm_final, cudaFuncAttributeMaxDynamicSharedMemorySize, SMEM_F);

    k_init  <<<(NN + 1023) / 1024, 1024>>>((const long long*)ei);
    k_count <<<(NE + 255) / 256, 256>>>(ei);
    k_scan1 <<<(NN + 1023) / 1024, 1024>>>();
    k_scan2 <<<1, 128>>>();
    k_scan3 <<<(NN + 1023) / 1024, 1024>>>();
    k_fill  <<<(NE + 255) / 256, 256>>>(ei);
    k_prepw <<<(3*2*128*128 + 384*64 + 255) / 256, 256>>>(Wl, Wr, fw);
    k_splitx0<<<(NN * 32 + 255) / 256, 256>>>(x);

    const int gemm_blocks = (NN + 127) / 128;
    for (int l = 0; l < 3; ++l) {
        k_agg<<<(NN * 32 + 255) / 256, 256>>>(l);
        k_gemm_layer<<<gemm_blocks, 256, SMEM_L>>>(b + (size_t)l * 128, l);
    }
    k_gemm_final<<<gemm_blocks, 256, SMEM_F>>>(fb, out);
}